// round 4
// baseline (speedup 1.0000x reference)
#include <cuda_runtime.h>
#include <float.h>
#include <math.h>

// Problem constants (fixed by reference setup_inputs)
#define BB 8
#define SS 4096
#define CC 1024
#define HH 64
#define NS 64           // S splits for partial reduction
#define SROWS (SS/NS)   // 64 rows per partial chunk

// Scratch (no allocations allowed in kernel_launch)
__device__ float g_psum[BB*NS*CC];
__device__ float g_pmax[BB*NS*CC];
__device__ int   g_pcnt[BB*NS];
__device__ float g_a   [BB*CC];

// ---------------------------------------------------------------------------
// Kernel 1: partial masked sum/max over a 64-row chunk, full 1024 channels.
// Valid rows compacted into smem list -> branch-free loop, 4 rows/iter for
// memory-level parallelism. grid (NS, BB), 256 threads.
// ---------------------------------------------------------------------------
__global__ void k_partial(const float* __restrict__ x,
                          const int*   __restrict__ mask) {
    const int ns = blockIdx.x;
    const int b  = blockIdx.y;
    const int c4 = threadIdx.x;              // float4 index 0..255

    __shared__ int smask[SROWS];
    __shared__ int srows[SROWS];
    __shared__ int snv;
    const int s0 = ns * SROWS;
    if (threadIdx.x < SROWS)
        smask[threadIdx.x] = mask[b * SS + s0 + threadIdx.x];
    __syncthreads();
    if (threadIdx.x == 0) {
        int nv = 0;
        #pragma unroll
        for (int i = 0; i < SROWS; i++)
            if (smask[i]) srows[nv++] = i;
        snv = nv;
        g_pcnt[b * NS + ns] = nv;
    }
    __syncthreads();
    const int nv = snv;

    float4 sum = make_float4(0.f, 0.f, 0.f, 0.f);
    float4 mx  = make_float4(-FLT_MAX, -FLT_MAX, -FLT_MAX, -FLT_MAX);

    const float4* xp = reinterpret_cast<const float4*>(
        x + ((size_t)b * SS + s0) * CC) + c4;

    int i = 0;
    for (; i + 4 <= nv; i += 4) {
        const int r0 = srows[i];
        const int r1 = srows[i + 1];
        const int r2 = srows[i + 2];
        const int r3 = srows[i + 3];
        float4 v0 = xp[(size_t)r0 * (CC / 4)];
        float4 v1 = xp[(size_t)r1 * (CC / 4)];
        float4 v2 = xp[(size_t)r2 * (CC / 4)];
        float4 v3 = xp[(size_t)r3 * (CC / 4)];
        sum.x += v0.x; sum.y += v0.y; sum.z += v0.z; sum.w += v0.w;
        mx.x = fmaxf(mx.x, v0.x); mx.y = fmaxf(mx.y, v0.y);
        mx.z = fmaxf(mx.z, v0.z); mx.w = fmaxf(mx.w, v0.w);
        sum.x += v1.x; sum.y += v1.y; sum.z += v1.z; sum.w += v1.w;
        mx.x = fmaxf(mx.x, v1.x); mx.y = fmaxf(mx.y, v1.y);
        mx.z = fmaxf(mx.z, v1.z); mx.w = fmaxf(mx.w, v1.w);
        sum.x += v2.x; sum.y += v2.y; sum.z += v2.z; sum.w += v2.w;
        mx.x = fmaxf(mx.x, v2.x); mx.y = fmaxf(mx.y, v2.y);
        mx.z = fmaxf(mx.z, v2.z); mx.w = fmaxf(mx.w, v2.w);
        sum.x += v3.x; sum.y += v3.y; sum.z += v3.z; sum.w += v3.w;
        mx.x = fmaxf(mx.x, v3.x); mx.y = fmaxf(mx.y, v3.y);
        mx.z = fmaxf(mx.z, v3.z); mx.w = fmaxf(mx.w, v3.w);
    }
    for (; i < nv; i++) {
        const int r0 = srows[i];
        float4 v0 = xp[(size_t)r0 * (CC / 4)];
        sum.x += v0.x; sum.y += v0.y; sum.z += v0.z; sum.w += v0.w;
        mx.x = fmaxf(mx.x, v0.x); mx.y = fmaxf(mx.y, v0.y);
        mx.z = fmaxf(mx.z, v0.z); mx.w = fmaxf(mx.w, v0.w);
    }

    reinterpret_cast<float4*>(g_psum + (b * NS + ns) * CC)[c4] = sum;
    reinterpret_cast<float4*>(g_pmax + (b * NS + ns) * CC)[c4] = mx;
}

// ---------------------------------------------------------------------------
// Kernel 2 (fused): fold partials -> mean/max (smem only), then
//   hsum = relu(mean@W0^T) + relu(max@W0^T), then a = sigmoid(hsum @ W1^T).
// grid = BB (8 blocks), 1024 threads (32 warps).
// ---------------------------------------------------------------------------
__global__ void __launch_bounds__(1024)
k_fused(const float* __restrict__ W0,     // [H, C]
        const float* __restrict__ W1) {   // [C, H]
    const int b = blockIdx.x;
    const int tid  = threadIdx.x;
    const int warp = tid >> 5;
    const int lane = tid & 31;

    __shared__ float smean[CC];
    __shared__ float smax [CC];
    __shared__ float hsum [HH];
    __shared__ float scount;

    // ---- Phase 1: fold NS partials (thread = channel) -------------------
    {
        float sum = 0.0f;
        float mx  = -FLT_MAX;
        const float* ps = g_psum + b * NS * CC + tid;
        const float* pm = g_pmax + b * NS * CC + tid;
        #pragma unroll 8
        for (int ns = 0; ns < NS; ns++) {
            sum += ps[ns * CC];
            mx = fmaxf(mx, pm[ns * CC]);
        }
        // count reduction (warp 0)
        if (warp == 0) {
            int c = (lane < 32) ? g_pcnt[b * NS + lane] + g_pcnt[b * NS + 32 + lane] : 0;
            #pragma unroll
            for (int off = 16; off > 0; off >>= 1)
                c += __shfl_xor_sync(0xFFFFFFFFu, c, off);
            if (lane == 0) scount = fmaxf((float)c, 1.0f);
        }
        smax[tid] = mx;
        __syncthreads();
        smean[tid] = sum / scount;
        __syncthreads();
    }

    // ---- Phase 2: hidden layer (one warp per 2 hidden units) ------------
    #pragma unroll
    for (int jj = 0; jj < 2; jj++) {
        const int j = warp + jj * 32;
        const float* w = W0 + j * CC;
        float dm = 0.0f, dx = 0.0f;
        #pragma unroll 8
        for (int k = lane; k < CC; k += 32) {
            float wv = w[k];
            dm += wv * smean[k];
            dx += wv * smax[k];
        }
        #pragma unroll
        for (int off = 16; off > 0; off >>= 1) {
            dm += __shfl_xor_sync(0xFFFFFFFFu, dm, off);
            dx += __shfl_xor_sync(0xFFFFFFFFu, dx, off);
        }
        if (lane == 0)
            hsum[j] = fmaxf(dm, 0.0f) + fmaxf(dx, 0.0f);
    }
    __syncthreads();

    // ---- Phase 3: output layer + sigmoid (thread = channel) -------------
    {
        const float4* w1 = reinterpret_cast<const float4*>(W1 + tid * HH);
        float acc = 0.0f;
        #pragma unroll
        for (int j = 0; j < HH / 4; j++) {
            float4 w = w1[j];
            acc += w.x * hsum[j * 4 + 0] + w.y * hsum[j * 4 + 1]
                 + w.z * hsum[j * 4 + 2] + w.w * hsum[j * 4 + 3];
        }
        g_a[b * CC + tid] = 1.0f / (1.0f + expf(-acc));
    }
}

// ---------------------------------------------------------------------------
// Kernel 3: out[b,s,c] = x[b,s,c] * a[b,c]   (float4 streaming, .cs hints)
// grid ((S*C/4)/256, B)
// ---------------------------------------------------------------------------
__global__ void k_scale(const float* __restrict__ x,
                        float*       __restrict__ out) {
    const int b = blockIdx.y;
    const unsigned i = blockIdx.x * blockDim.x + threadIdx.x;  // float4 idx
    const unsigned c4 = i & (CC / 4 - 1);                       // 0..255

    const size_t gi = (size_t)b * (SS * CC / 4) + i;
    float4 v = __ldcs(reinterpret_cast<const float4*>(x) + gi);
    float4 a = reinterpret_cast<const float4*>(g_a + b * CC)[c4];
    v.x *= a.x; v.y *= a.y; v.z *= a.z; v.w *= a.w;
    __stcs(reinterpret_cast<float4*>(out) + gi, v);
}

// ---------------------------------------------------------------------------
extern "C" void kernel_launch(void* const* d_in, const int* in_sizes, int n_in,
                              void* d_out, int out_size) {
    const float* x    = (const float*)d_in[0];   // [B,S,C]
    const int*   mask = (const int*)  d_in[1];   // [B,S]
    const float* W0   = (const float*)d_in[2];   // [H,C]
    const float* W1   = (const float*)d_in[3];   // [C,H]
    float*       out  = (float*)d_out;           // [B,S,C]

    (void)in_sizes; (void)n_in; (void)out_size;

    {   dim3 grid(NS, BB);                  k_partial<<<grid, 256>>>(x, mask); }
    {   k_fused<<<BB, 1024>>>(W0, W1); }
    {   dim3 grid((SS * CC / 4) / 256, BB); k_scale<<<grid, 256>>>(x, out);    }
}